// round 11
// baseline (speedup 1.0000x reference)
#include <cuda_runtime.h>
#include <cuda_bf16.h>
#include <stdint.h>

// Problem constants
#define BATCH 16
#define DIM   256
#define HW    4096          // 64*64
#define NROWS 65536         // BATCH*HW
#define KCODE 1024
#define NOUT  16777216      // BATCH*DIM*HW
#define BM    128           // rows per block
#define BN    128           // codes per tile
#define ZS_STRIDE 132
#define ES_STRIDE 132

// Scratch: transposed embedding, accurate norms, loss accumulator
__device__ float  g_embT[DIM * KCODE];   // [d][k]
__device__ float  g_en[KCODE];           // fl32(sum_d fl32(emb^2)) via double accum
__device__ float  g_zn[NROWS];           // fl32(sum_d fl32(z^2))   via double accum
__device__ double g_loss;

// ---------------------------------------------------------------------------
// Prep 1: transpose emb [K,D] -> embT [D,K] via 32x32 smem tiles; zero loss.
// ---------------------------------------------------------------------------
__global__ void vq_prep_transpose(const float* __restrict__ emb) {
    __shared__ float tile[32][33];
    const int kt = blockIdx.x & 31;
    const int dt = blockIdx.x >> 5;
    const int lx = threadIdx.x & 31;
    const int ly = threadIdx.x >> 5;
    #pragma unroll
    for (int r = 0; r < 32; r += 8)
        tile[ly + r][lx] = emb[(size_t)(kt * 32 + ly + r) * DIM + dt * 32 + lx];
    __syncthreads();
    #pragma unroll
    for (int r = 0; r < 32; r += 8)
        g_embT[(size_t)(dt * 32 + ly + r) * KCODE + kt * 32 + lx] = tile[lx][ly + r];
    if (blockIdx.x == 0 && threadIdx.x == 0) g_loss = 0.0;
}

// ---------------------------------------------------------------------------
// Prep 2: en[k] = round_f32( sum_d (double)fl32(emb[k][d]^2) ).
// Mimics reference's elementwise fp32 square, with order-free accurate sum.
// ---------------------------------------------------------------------------
__global__ void vq_prep_en(const float* __restrict__ emb) {
    int k = blockIdx.x * 256 + threadIdx.x;
    double s = 0.0;
    const float* er = emb + (size_t)k * DIM;
    #pragma unroll 8
    for (int d = 0; d < DIM; ++d) {
        float v = er[d];
        float sq = __fmul_rn(v, v);     // fp32-rounded square, like XLA elementwise
        s += (double)sq;
    }
    g_en[k] = (float)s;
}

// ---------------------------------------------------------------------------
// Prep 3: zn[row] = round_f32( sum_d (double)fl32(z^2) ), row-major over pixels.
// z layout NCHW: z[b][d][hw]; warp reads are coalesced over hw.
// ---------------------------------------------------------------------------
__global__ void vq_prep_zn(const float* __restrict__ z) {
    int row = blockIdx.x * 256 + threadIdx.x;   // row = b*HW + hw
    int b = row >> 12;
    int hw = row & 4095;
    const float* zp = z + ((size_t)b * DIM) * HW + hw;
    double s = 0.0;
    #pragma unroll 8
    for (int d = 0; d < DIM; ++d) {
        float v = zp[(size_t)d * HW];
        float sq = __fmul_rn(v, v);
        s += (double)sq;
    }
    g_zn[row] = (float)s;
}

// ---------------------------------------------------------------------------
// Main: fused distance GEMM + quantization-faithful score + argmin + gather +
// straight-through + loss. One block = 128 rows x all 1024 codes, 256 threads,
// 8x8 micro-tile. Score replicates reference association:
//   s = fl( fl(zn + en_k) - fl(2*m_k) )   (both adds in fp32, no contraction)
// m accumulated as a strictly sequential fmaf chain over d=0..255.
// ---------------------------------------------------------------------------
__global__ __launch_bounds__(256, 1)
void vq_main(const float* __restrict__ z, const float* __restrict__ emb,
             float* __restrict__ out, int write_idx) {
    extern __shared__ float sm[];
    float* zs = sm;                                   // 256*132 floats
    float* es = zs + DIM * ZS_STRIDE;                 // 32*132 floats
    unsigned long long* rp = (unsigned long long*)(es + 32 * ES_STRIDE); // 128
    int*   sidx = (int*)(rp + BM);                    // 128
    float* red  = (float*)(sidx + BM);                // 8

    const int t = threadIdx.x;
    const int row0 = blockIdx.x * BM;
    const int b   = row0 >> 12;
    const int hw0 = row0 & 4095;
    const float* zb = z + ((size_t)b * DIM) * HW + hw0;

    // Stage z tile: zs[d][row], coalesced float4 over rows
    for (int i = t; i < DIM * (BM / 4); i += 256) {
        int d  = i >> 5;
        int r4 = (i & 31) << 2;
        float4 v = *(const float4*)(zb + (size_t)d * HW + r4);
        *(float4*)(zs + d * ZS_STRIDE + r4) = v;
    }
    if (t < BM) rp[t] = 0xFFFFFFFFFFFFFFFFULL;

    const int tx = t & 15;
    const int ty = t >> 4;
    const int rbase = ty * 8;
    const int cbase = tx * 8;

    // per-thread row norms (constant across kt)
    float zn8[8];
    #pragma unroll
    for (int ii = 0; ii < 8; ++ii) zn8[ii] = g_zn[row0 + rbase + ii];

    // es staging: each thread owns 4 float4 slots
    const int sdd0 = t >> 5;
    const int sc4  = (t & 31) << 2;

    float4 pf[4];
    #pragma unroll
    for (int p = 0; p < 4; ++p)
        pf[p] = *(const float4*)(g_embT + (size_t)(sdd0 + p * 8) * KCODE + sc4);

    for (int kt = 0; kt < KCODE / BN; ++kt) {
        float acc[8][8];
        #pragma unroll
        for (int ii = 0; ii < 8; ++ii)
            #pragma unroll
            for (int jj = 0; jj < 8; ++jj) acc[ii][jj] = 0.f;

        for (int dc = 0; dc < DIM / 32; ++dc) {
            __syncthreads();
            #pragma unroll
            for (int p = 0; p < 4; ++p)
                *(float4*)(es + (sdd0 + p * 8) * ES_STRIDE + sc4) = pf[p];
            __syncthreads();

            int ndc = dc + 1, nkt = kt;
            if (ndc == DIM / 32) { ndc = 0; nkt = kt + 1; }
            if (nkt < KCODE / BN) {
                #pragma unroll
                for (int p = 0; p < 4; ++p)
                    pf[p] = *(const float4*)(g_embT +
                        (size_t)(ndc * 32 + sdd0 + p * 8) * KCODE + nkt * BN + sc4);
            }

            #pragma unroll 8
            for (int dd = 0; dd < 32; ++dd) {
                float a[8], bb[8];
                const float* zr = zs + (dc * 32 + dd) * ZS_STRIDE + rbase;
                const float* er = es + dd * ES_STRIDE + cbase;
                *(float4*)(a)      = *(const float4*)(zr);
                *(float4*)(a + 4)  = *(const float4*)(zr + 4);
                *(float4*)(bb)     = *(const float4*)(er);
                *(float4*)(bb + 4) = *(const float4*)(er + 4);
                #pragma unroll
                for (int ii = 0; ii < 8; ++ii)
                    #pragma unroll
                    for (int jj = 0; jj < 8; ++jj)
                        acc[ii][jj] = fmaf(a[ii], bb[jj], acc[ii][jj]);
            }
        }

        // Reference-faithful score: s = fl(fl(zn+en) - 2m); argmin via atomicMin
        float en8[8];
        *(float4*)(en8)     = *(const float4*)(g_en + kt * BN + cbase);
        *(float4*)(en8 + 4) = *(const float4*)(g_en + kt * BN + cbase + 4);
        #pragma unroll
        for (int ii = 0; ii < 8; ++ii) {
            float best;
            int bj = 0;
            {
                float A = __fadd_rn(zn8[ii], en8[0]);
                best = __fadd_rn(A, __fmul_rn(-2.f, acc[ii][0]));
            }
            #pragma unroll
            for (int jj = 1; jj < 8; ++jj) {
                float A = __fadd_rn(zn8[ii], en8[jj]);
                float s = __fadd_rn(A, __fmul_rn(-2.f, acc[ii][jj]));
                if (s < best) { best = s; bj = jj; }   // strict <: first index on ties
            }
            unsigned int u = __float_as_uint(best);
            u = (u & 0x80000000u) ? ~u : (u | 0x80000000u);
            unsigned long long pk =
                ((unsigned long long)u << 32) | (unsigned)(kt * BN + cbase + bj);
            atomicMin(&rp[rbase + ii], pk);
        }
    }
    __syncthreads();
    if (t < BM) sidx[t] = (int)(rp[t] & 0xFFFFFFFFULL);
    __syncthreads();

    // Epilogue: gather z_q, straight-through output, loss partial
    const int i  = t & 127;
    const int ch = t >> 7;
    const int code = sidx[i];
    const float* er = emb + (size_t)code * DIM;
    float* ob = out + ((size_t)b * DIM) * HW + hw0 + i;
    float lsum = 0.f;
    #pragma unroll 4
    for (int c = ch; c < DIM; c += 2) {
        float zv = zs[c * ZS_STRIDE + i];
        float q  = __ldg(er + c);
        float dq = __fadd_rn(q, -zv);
        lsum = fmaf(dq, dq, lsum);
        ob[(size_t)c * HW] = __fadd_rn(zv, dq);   // z + sg(zq - z), ref fp ordering
    }
    if (write_idx && ch == 0)
        out[(size_t)NOUT + row0 + i] = (float)code;

    #pragma unroll
    for (int off = 16; off > 0; off >>= 1)
        lsum += __shfl_xor_sync(0xFFFFFFFFu, lsum, off);
    if ((t & 31) == 0) red[t >> 5] = lsum;
    __syncthreads();
    if (t == 0) {
        float s = 0.f;
        #pragma unroll
        for (int w = 0; w < 8; ++w) s += red[w];
        atomicAdd(&g_loss, (double)s);
    }
}

// ---------------------------------------------------------------------------
// Finalize: loss = BETA * mean((zq - z)^2); first reference term is exactly 0.
// ---------------------------------------------------------------------------
__global__ void vq_finalize(float* __restrict__ out, int pos) {
    out[pos] = (float)(0.25 * g_loss * (1.0 / 16777216.0));
}

extern "C" void kernel_launch(void* const* d_in, const int* in_sizes, int n_in,
                              void* d_out, int out_size) {
    const float* z   = (const float*)d_in[0];
    const float* emb = (const float*)d_in[1];
    float* out = (float*)d_out;

    const int write_idx  = (out_size >= NOUT + NROWS) ? 1 : 0;
    const int write_loss = (out_size >= NOUT + NROWS + 1) ? 1 : 0;

    static const int SMEM_BYTES =
        (DIM * ZS_STRIDE + 32 * ES_STRIDE) * 4 + BM * 8 + BM * 4 + 8 * 4;
    cudaFuncSetAttribute(vq_main, cudaFuncAttributeMaxDynamicSharedMemorySize,
                         SMEM_BYTES);

    vq_prep_transpose<<<256, 256>>>(emb);
    vq_prep_en<<<KCODE / 256, 256>>>(emb);
    vq_prep_zn<<<NROWS / 256, 256>>>(z);
    vq_main<<<NROWS / BM, 256, SMEM_BYTES>>>(z, emb, out, write_idx);
    if (write_loss)
        vq_finalize<<<1, 1>>>(out, NOUT + NROWS);
}